// round 1
// baseline (speedup 1.0000x reference)
#include <cuda_runtime.h>
#include <cuda_bf16.h>
#include <math.h>

// ---------------- problem constants ----------------
#define NTOK   4096          // B*S = 2*2048
#define HDIM   4096
#define NEXP   8
#define TOPK   2
#define CAP    1536          // int(B*S*1.5*K/E)
#define NSEL   (NTOK*TOPK)   // 8192

#define DISPATCH_ELEMS  ((long long)NTOK*NEXP*CAP)       // 50331648
#define PROBS_OFF       (2LL*DISPATCH_ELEMS)             // 100663296
#define AUX_OFF         (PROBS_OFF + (long long)NTOK*NEXP)

// ---------------- device scratch (no allocations allowed) ----------------
__device__ float g_h[(size_t)NTOK * HDIM];      // 64 MB intermediate h = relu(x@W1+b1)
__device__ float g_logits[NTOK * NEXP];
__device__ int   g_flat_idx[NSEL];
__device__ float g_flat_prob[NSEL];
__device__ int   g_pos[NSEL];
__device__ int   g_counts[NEXP];

// ---------------- zero output + counters ----------------
__global__ void zero_kernel(float4* __restrict__ p, long long n4) {
    long long i = blockIdx.x * (long long)blockDim.x + threadIdx.x;
    long long stride = gridDim.x * (long long)blockDim.x;
    float4 z = make_float4(0.f, 0.f, 0.f, 0.f);
    for (; i < n4; i += stride) p[i] = z;
    if (blockIdx.x == 0 && threadIdx.x < NEXP) g_counts[threadIdx.x] = 0;
}

// ---------------- GEMM1: h = relu(x @ W1 + b1) ----------------
// A[M,K] row-major, B[K,N] row-major, M=N=K=4096. 128x128x16 tile, 256 thr, 8x8 microtile.
#define BM 128
#define BN 128
#define BKK 16
__global__ __launch_bounds__(256) void gemm1_kernel(
    const float* __restrict__ A, const float* __restrict__ B,
    const float* __restrict__ bias, float* __restrict__ C)
{
    __shared__ float As[BKK][BM + 4];
    __shared__ float Bs[BKK][BN];
    const int tid = threadIdx.x;
    const int tx = tid & 15;        // 0..15  -> col group
    const int ty = tid >> 4;        // 0..15  -> row group
    const int row0 = blockIdx.y * BM;
    const int col0 = blockIdx.x * BN;

    float acc[8][8];
    #pragma unroll
    for (int i = 0; i < 8; i++)
        #pragma unroll
        for (int j = 0; j < 8; j++) acc[i][j] = 0.f;

    for (int kt = 0; kt < HDIM; kt += BKK) {
        // load A tile 128x16 (512 float4, 2 per thread), store transposed
        #pragma unroll
        for (int l = 0; l < 2; l++) {
            int idx = tid + l * 256;
            int r = idx >> 2, c4 = idx & 3;
            float4 a = *(const float4*)(A + (size_t)(row0 + r) * HDIM + kt + c4 * 4);
            As[c4 * 4 + 0][r] = a.x;
            As[c4 * 4 + 1][r] = a.y;
            As[c4 * 4 + 2][r] = a.z;
            As[c4 * 4 + 3][r] = a.w;
        }
        // load B tile 16x128 (512 float4, 2 per thread), coalesced
        #pragma unroll
        for (int l = 0; l < 2; l++) {
            int idx = tid + l * 256;
            int r = idx >> 5, c4 = idx & 31;
            *(float4*)(&Bs[r][c4 * 4]) =
                *(const float4*)(B + (size_t)(kt + r) * HDIM + col0 + c4 * 4);
        }
        __syncthreads();

        #pragma unroll
        for (int bk = 0; bk < BKK; bk++) {
            float a[8], b[8];
            #pragma unroll
            for (int i = 0; i < 8; i++) a[i] = As[bk][ty * 8 + i];
            #pragma unroll
            for (int j = 0; j < 8; j++) b[j] = Bs[bk][tx * 8 + j];
            #pragma unroll
            for (int i = 0; i < 8; i++)
                #pragma unroll
                for (int j = 0; j < 8; j++) acc[i][j] += a[i] * b[j];
        }
        __syncthreads();
    }

    // epilogue: relu(acc + bias), vectorized stores
    #pragma unroll
    for (int i = 0; i < 8; i++) {
        int r = row0 + ty * 8 + i;
        #pragma unroll
        for (int j = 0; j < 8; j += 4) {
            int c = col0 + tx * 8 + j;
            float4 v;
            v.x = fmaxf(acc[i][j + 0] + bias[c + 0], 0.f);
            v.y = fmaxf(acc[i][j + 1] + bias[c + 1], 0.f);
            v.z = fmaxf(acc[i][j + 2] + bias[c + 2], 0.f);
            v.w = fmaxf(acc[i][j + 3] + bias[c + 3], 0.f);
            *(float4*)(C + (size_t)r * HDIM + c) = v;
        }
    }
}

// ---------------- GEMM2: logits = h @ W2 + b2  (one warp per token) ----------------
__global__ void gemm2_kernel(const float* __restrict__ h, const float* __restrict__ W2,
                             const float* __restrict__ b2, float* __restrict__ logits)
{
    int warp = (blockIdx.x * blockDim.x + threadIdx.x) >> 5;
    int lane = threadIdx.x & 31;
    if (warp >= NTOK) return;
    const float* hr = h + (size_t)warp * HDIM;

    float acc[NEXP];
    #pragma unroll
    for (int e = 0; e < NEXP; e++) acc[e] = 0.f;

    for (int k0 = lane * 4; k0 < HDIM; k0 += 128) {
        float4 hv = *(const float4*)(hr + k0);
        float hvv[4] = {hv.x, hv.y, hv.z, hv.w};
        #pragma unroll
        for (int j = 0; j < 4; j++) {
            const float* w = W2 + (size_t)(k0 + j) * NEXP;
            float4 w0 = *(const float4*)w;
            float4 w1 = *(const float4*)(w + 4);
            acc[0] += hvv[j] * w0.x; acc[1] += hvv[j] * w0.y;
            acc[2] += hvv[j] * w0.z; acc[3] += hvv[j] * w0.w;
            acc[4] += hvv[j] * w1.x; acc[5] += hvv[j] * w1.y;
            acc[6] += hvv[j] * w1.z; acc[7] += hvv[j] * w1.w;
        }
    }
    #pragma unroll
    for (int e = 0; e < NEXP; e++) {
        #pragma unroll
        for (int off = 16; off > 0; off >>= 1)
            acc[e] += __shfl_down_sync(0xffffffffu, acc[e], off);
    }
    if (lane == 0) {
        #pragma unroll
        for (int e = 0; e < NEXP; e++)
            logits[warp * NEXP + e] = acc[e] + b2[e];
    }
}

// ---------------- softmax + top-2 (tie -> lower index) ----------------
__global__ void topk_kernel(const float* __restrict__ logits, float* __restrict__ probs_out)
{
    int t = blockIdx.x * blockDim.x + threadIdx.x;
    if (t >= NTOK) return;
    float l[NEXP];
    float m = -1e30f;
    #pragma unroll
    for (int e = 0; e < NEXP; e++) { l[e] = logits[t * NEXP + e]; m = fmaxf(m, l[e]); }
    float s = 0.f;
    #pragma unroll
    for (int e = 0; e < NEXP; e++) { l[e] = expf(l[e] - m); s += l[e]; }
    float inv = 1.f / s;
    float p[NEXP];
    #pragma unroll
    for (int e = 0; e < NEXP; e++) { p[e] = l[e] * inv; probs_out[t * NEXP + e] = p[e]; }

    int i1 = 0; float p1 = p[0];
    #pragma unroll
    for (int e = 1; e < NEXP; e++) if (p[e] > p1) { p1 = p[e]; i1 = e; }
    int i2 = -1; float p2 = -1.f;
    #pragma unroll
    for (int e = 0; e < NEXP; e++) if (e != i1 && p[e] > p2) { p2 = p[e]; i2 = e; }

    float norm = 1.f / (p1 + p2 + 1e-8f);
    g_flat_idx[2 * t + 0] = i1;
    g_flat_idx[2 * t + 1] = i2;
    g_flat_prob[2 * t + 0] = p1 * norm;
    g_flat_prob[2 * t + 1] = p2 * norm;
    atomicAdd(&g_counts[i1], 1);   // integer atomics: deterministic
    atomicAdd(&g_counts[i2], 1);
}

// ---------------- exclusive per-expert position scan over N=8192 picks ----------------
// 8 experts x 16-bit counters packed in uint4; counts <= 8192 so packed adds never carry.
__device__ __forceinline__ uint4 add4(uint4 a, uint4 b) {
    return make_uint4(a.x + b.x, a.y + b.y, a.z + b.z, a.w + b.w);
}
__device__ __forceinline__ uint4 sub4(uint4 a, uint4 b) {
    return make_uint4(a.x - b.x, a.y - b.y, a.z - b.z, a.w - b.w);
}
__global__ __launch_bounds__(1024) void scan_kernel()
{
    const int tid = threadIdx.x;
    const int lane = tid & 31, wid = tid >> 5;

    int e[8];
    uint4 pre[8];
    uint4 run = make_uint4(0, 0, 0, 0);
    #pragma unroll
    for (int i = 0; i < 8; i++) {
        e[i] = g_flat_idx[tid * 8 + i];
        pre[i] = run;
        unsigned word = (unsigned)e[i] >> 1;
        unsigned add = 1u << ((e[i] & 1) * 16);
        if (word == 0) run.x += add;
        else if (word == 1) run.y += add;
        else if (word == 2) run.z += add;
        else run.w += add;
    }
    const uint4 own = run;

    // warp inclusive scan
    uint4 incl = own;
    #pragma unroll
    for (int off = 1; off < 32; off <<= 1) {
        unsigned vx = __shfl_up_sync(0xffffffffu, incl.x, off);
        unsigned vy = __shfl_up_sync(0xffffffffu, incl.y, off);
        unsigned vz = __shfl_up_sync(0xffffffffu, incl.z, off);
        unsigned vw = __shfl_up_sync(0xffffffffu, incl.w, off);
        if (lane >= off) { incl.x += vx; incl.y += vy; incl.z += vz; incl.w += vw; }
    }

    __shared__ uint4 wtot[32];
    if (lane == 31) wtot[wid] = incl;
    __syncthreads();
    if (wid == 0) {
        uint4 v = wtot[lane];
        uint4 inc2 = v;
        #pragma unroll
        for (int off = 1; off < 32; off <<= 1) {
            unsigned vx = __shfl_up_sync(0xffffffffu, inc2.x, off);
            unsigned vy = __shfl_up_sync(0xffffffffu, inc2.y, off);
            unsigned vz = __shfl_up_sync(0xffffffffu, inc2.z, off);
            unsigned vw = __shfl_up_sync(0xffffffffu, inc2.w, off);
            if (lane >= off) { inc2.x += vx; inc2.y += vy; inc2.z += vz; inc2.w += vw; }
        }
        wtot[lane] = sub4(inc2, v);   // exclusive warp prefix
    }
    __syncthreads();

    const uint4 base = add4(wtot[wid], sub4(incl, own));  // block-exclusive prefix for thread
    #pragma unroll
    for (int i = 0; i < 8; i++) {
        uint4 tot = add4(base, pre[i]);
        unsigned word = (unsigned)e[i] >> 1;
        unsigned w = (word == 0) ? tot.x : (word == 1) ? tot.y : (word == 2) ? tot.z : tot.w;
        g_pos[tid * 8 + i] = (int)((w >> ((e[i] & 1) * 16)) & 0xFFFFu);
    }
}

// ---------------- scatter kept picks into dispatch / combine ----------------
__global__ void scatter_kernel(float* __restrict__ dispatch, float* __restrict__ combine)
{
    int n = blockIdx.x * blockDim.x + threadIdx.x;
    if (n >= NSEL) return;
    int p = g_pos[n];
    if (p < CAP) {
        int tok = n >> 1;
        int e = g_flat_idx[n];
        size_t off = ((size_t)tok * NEXP + e) * CAP + p;
        dispatch[off] = 1.0f;
        combine[off] = g_flat_prob[n];
    }
}

// ---------------- aux loss (deterministic fixed-order reduction) ----------------
__global__ void aux_kernel(const float* __restrict__ probs, float* __restrict__ aux_out)
{
    __shared__ float sh[256];
    const int tid = threadIdx.x;
    float local[NEXP];
    #pragma unroll
    for (int e = 0; e < NEXP; e++) local[e] = 0.f;
    for (int t = tid; t < NTOK; t += 256) {
        #pragma unroll
        for (int e = 0; e < NEXP; e++) local[e] += probs[t * NEXP + e];
    }
    float aux = 0.f;
    for (int e = 0; e < NEXP; e++) {
        sh[tid] = local[e];
        __syncthreads();
        for (int s = 128; s > 0; s >>= 1) {
            if (tid < s) sh[tid] += sh[tid + s];
            __syncthreads();
        }
        if (tid == 0)
            aux += (sh[0] / (float)NTOK) * ((float)g_counts[e] / (float)NSEL) * (float)NEXP;
        __syncthreads();
    }
    if (tid == 0) *aux_out = aux;
}

// ---------------- launch ----------------
extern "C" void kernel_launch(void* const* d_in, const int* in_sizes, int n_in,
                              void* d_out, int out_size)
{
    const float* x  = (const float*)d_in[0];
    const float* W1 = (const float*)d_in[1];
    const float* b1 = (const float*)d_in[2];
    const float* W2 = (const float*)d_in[3];
    const float* b2 = (const float*)d_in[4];

    float* out      = (float*)d_out;
    float* dispatch = out;
    float* combine  = out + DISPATCH_ELEMS;
    float* probs    = out + PROBS_OFF;
    float* aux      = out + AUX_OFF;

    // resolve device scratch symbols (no allocation; just address queries at first call
    // are not possible inside capture -> reference globals directly via kernels below)
    float* d_h;      cudaGetSymbolAddress((void**)&d_h, g_h);
    float* d_logits; cudaGetSymbolAddress((void**)&d_logits, g_logits);

    // 1) zero dispatch + combine (+ counters)
    zero_kernel<<<4096, 256>>>((float4*)out, (2LL * DISPATCH_ELEMS) / 4);

    // 2) GEMM1: h = relu(x@W1 + b1)
    dim3 g1(HDIM / BN, NTOK / BM);
    gemm1_kernel<<<g1, 256>>>(x, W1, b1, d_h);

    // 3) GEMM2: logits = h@W2 + b2
    gemm2_kernel<<<NTOK / 8, 256>>>(d_h, W2, b2, d_logits);

    // 4) softmax + top-2
    topk_kernel<<<NTOK / 256, 256>>>(d_logits, probs);

    // 5) capacity position scan
    scan_kernel<<<1, 1024>>>();

    // 6) scatter
    scatter_kernel<<<NSEL / 256, 256>>>(dispatch, combine);

    // 7) aux loss
    aux_kernel<<<1, 256>>>(probs, aux);
}

// round 4
// speedup vs baseline: 1.5886x; 1.5886x over previous
#include <cuda_runtime.h>
#include <cuda.h>
#include <math.h>
#include <cstdint>

// ---------------- problem constants ----------------
#define NTOK   4096          // B*S
#define HDIM   4096
#define NEXP   8
#define TOPK   2
#define CAP    1536
#define NSEL   (NTOK*TOPK)

#define DISPATCH_ELEMS  ((long long)NTOK*NEXP*CAP)
#define PROBS_OFF       (2LL*DISPATCH_ELEMS)
#define AUX_OFF         (PROBS_OFF + (long long)NTOK*NEXP)

// ---------------- device scratch ----------------
__device__ float g_h[(size_t)NTOK * HDIM];
__device__ float g_logits[NTOK * NEXP];
__device__ int   g_flat_idx[NSEL];
__device__ float g_flat_prob[NSEL];
__device__ int   g_pos[NSEL];
__device__ int   g_counts[NEXP];

// ---------------- helpers ----------------
__device__ __forceinline__ void cpasync16(uint32_t dst, const void* src) {
    asm volatile("cp.async.cg.shared.global [%0], [%1], 16;\n" :: "r"(dst), "l"(src));
}
#define CP_COMMIT() asm volatile("cp.async.commit_group;\n" ::: "memory")
#define CP_WAIT(n)  asm volatile("cp.async.wait_group %0;\n" :: "n"(n) : "memory")

__device__ __forceinline__ uint32_t smem_u32(const void* p) {
    uint32_t a;
    asm("{ .reg .u64 t; cvta.to.shared.u64 t, %1; cvt.u32.u64 %0, t; }" : "=r"(a) : "l"(p));
    return a;
}

__device__ __forceinline__ float tf32_hi(float v) {
    return __uint_as_float(__float_as_uint(v) & 0xFFFFE000u);
}

// mma.sync m16n8k8 tf32: D += A x B, fp32 accum. Base ISA (sm_80+), no 'a' features.
__device__ __forceinline__ void mma_tf32(float c[4],
                                         uint32_t a0, uint32_t a1, uint32_t a2, uint32_t a3,
                                         uint32_t b0, uint32_t b1) {
    asm volatile(
        "mma.sync.aligned.m16n8k8.row.col.f32.tf32.tf32.f32 "
        "{%0,%1,%2,%3}, {%4,%5,%6,%7}, {%8,%9}, {%0,%1,%2,%3};"
        : "+f"(c[0]), "+f"(c[1]), "+f"(c[2]), "+f"(c[3])
        : "r"(a0), "r"(a1), "r"(a2), "r"(a3), "r"(b0), "r"(b1));
}

// ---------------- zero output + counters ----------------
__global__ void zero_kernel(float4* __restrict__ p, long long n4) {
    long long i = blockIdx.x * (long long)blockDim.x + threadIdx.x;
    long long stride = gridDim.x * (long long)blockDim.x;
    float4 z = make_float4(0.f, 0.f, 0.f, 0.f);
    for (; i < n4; i += stride) p[i] = z;
    if (blockIdx.x == 0 && threadIdx.x < NEXP) g_counts[threadIdx.x] = 0;
}

// ---------------- GEMM1: h = relu(x @ W1 + b1), 3xTF32 mma.sync ----------------
// A[M,K] row-major, W1[K,N] row-major (used as col-major B for .row.col mma).
#define BM 128
#define BN 128
#define BK 32
#define ASTRIDE 36     // floats per A smem row (pad 4) -> conflict-free A frag
#define BSTRIDE 136    // floats per B smem row (pad 8) -> conflict-free B frag
#define ABYTES (BM * ASTRIDE * 4)     // 18432
#define BBYTES (BK * BSTRIDE * 4)     // 17408
#define STAGEBYTES (ABYTES + BBYTES)  // 35840
#define GSMEM (2 * STAGEBYTES)        // 71680

__global__ __launch_bounds__(256) void gemm1_tc(
    const float* __restrict__ A, const float* __restrict__ B,
    const float* __restrict__ bias, float* __restrict__ C)
{
    extern __shared__ float smem[];
    const int tid = threadIdx.x;
    const int warp = tid >> 5, lane = tid & 31;
    const int wm = (warp & 1) * 64;       // warp m-offset within CTA tile
    const int wn = (warp >> 1) * 32;      // warp n-offset
    const int row0 = blockIdx.y * BM;
    const int col0 = blockIdx.x * BN;
    const int r = lane >> 2, cq = lane & 3;

    const uint32_t sb = smem_u32(smem);

    float acc[4][4][4];   // [mtile][ntile][frag]
    #pragma unroll
    for (int i = 0; i < 4; i++)
        #pragma unroll
        for (int j = 0; j < 4; j++)
            #pragma unroll
            for (int f = 0; f < 4; f++) acc[i][j][f] = 0.f;

    // ---- stage fill: A tile BMxBK, B tile BKxBN ----
    auto fill = [&](int buf, int kc) {
        const uint32_t st = sb + buf * STAGEBYTES;
        #pragma unroll
        for (int t = 0; t < 4; t++) {          // A: 1024 x 16B chunks
            int o = tid + t * 256;
            int rr = o >> 3, c16 = o & 7;
            cpasync16(st + (rr * ASTRIDE + c16 * 4) * 4,
                      A + (size_t)(row0 + rr) * HDIM + kc + c16 * 4);
        }
        #pragma unroll
        for (int t = 0; t < 4; t++) {          // B: 1024 x 16B chunks
            int o = tid + t * 256;
            int rr = o >> 5, c16 = o & 31;
            cpasync16(st + ABYTES + (rr * BSTRIDE + c16 * 4) * 4,
                      B + (size_t)(kc + rr) * HDIM + col0 + c16 * 4);
        }
    };

    fill(0, 0);
    CP_COMMIT();

    const int NCHUNK = HDIM / BK;   // 128
    for (int c = 0; c < NCHUNK; ++c) {
        if (c + 1 < NCHUNK) { fill((c + 1) & 1, (c + 1) * BK); CP_COMMIT(); CP_WAIT(1); }
        else                { CP_WAIT(0); }
        __syncthreads();

        const float* As = smem + ((c & 1) * STAGEBYTES) / 4;
        const float* Bs = As + ABYTES / 4;

        #pragma unroll
        for (int kk = 0; kk < BK; kk += 8) {
            // A fragments: 4 mtiles x 4 regs; split hi/lo in registers.
            // PTX m16n8k8 tf32 A layout:
            //   a0=(r, cq)  a1=(r+8, cq)  a2=(r, cq+4)  a3=(r+8, cq+4)
            uint32_t ahi[4][4], alo[4][4];
            #pragma unroll
            for (int mt = 0; mt < 4; mt++) {
                const float* pa = As + (size_t)(wm + mt * 16 + r) * ASTRIDE + kk + cq;
                float a0 = pa[0];
                float a1 = pa[8 * ASTRIDE];
                float a2 = pa[4];
                float a3 = pa[8 * ASTRIDE + 4];
                float h0 = tf32_hi(a0), h1 = tf32_hi(a1), h2 = tf32_hi(a2), h3 = tf32_hi(a3);
                ahi[mt][0] = __float_as_uint(h0); alo[mt][0] = __float_as_uint(a0 - h0);
                ahi[mt][1] = __float_as_uint(h1); alo[mt][1] = __float_as_uint(a1 - h1);
                ahi[mt][2] = __float_as_uint(h2); alo[mt][2] = __float_as_uint(a2 - h2);
                ahi[mt][3] = __float_as_uint(h3); alo[mt][3] = __float_as_uint(a3 - h3);
            }
            // B fragments: 4 ntiles x 2 regs: b0=(k=cq, n=r), b1=(k=cq+4, n=r)
            uint32_t bhi[4][2], blo[4][2];
            #pragma unroll
            for (int nt = 0; nt < 4; nt++) {
                const float* pb = Bs + (size_t)(kk + cq) * BSTRIDE + wn + nt * 8 + r;
                float b0 = pb[0], b1 = pb[4 * BSTRIDE];
                float h0 = tf32_hi(b0), h1 = tf32_hi(b1);
                bhi[nt][0] = __float_as_uint(h0); blo[nt][0] = __float_as_uint(b0 - h0);
                bhi[nt][1] = __float_as_uint(h1); blo[nt][1] = __float_as_uint(b1 - h1);
            }
            // 3x-split mma
            #pragma unroll
            for (int mt = 0; mt < 4; mt++)
                #pragma unroll
                for (int nt = 0; nt < 4; nt++) {
                    mma_tf32(acc[mt][nt], ahi[mt][0], ahi[mt][1], ahi[mt][2], ahi[mt][3],
                             bhi[nt][0], bhi[nt][1]);
                    mma_tf32(acc[mt][nt], ahi[mt][0], ahi[mt][1], ahi[mt][2], ahi[mt][3],
                             blo[nt][0], blo[nt][1]);
                    mma_tf32(acc[mt][nt], alo[mt][0], alo[mt][1], alo[mt][2], alo[mt][3],
                             bhi[nt][0], bhi[nt][1]);
                }
        }
        __syncthreads();
    }

    // ---- epilogue: relu(acc + bias) -> C ----
    // C frag: c0=(r, 2cq) c1=(r, 2cq+1) c2=(r+8, 2cq) c3=(r+8, 2cq+1)
    #pragma unroll
    for (int mt = 0; mt < 4; mt++) {
        #pragma unroll
        for (int nt = 0; nt < 4; nt++) {
            int col = col0 + wn + nt * 8 + 2 * cq;
            float bx = __ldg(bias + col), by = __ldg(bias + col + 1);
            int rowa = row0 + wm + mt * 16 + r;
            float2 v0, v1;
            v0.x = fmaxf(acc[mt][nt][0] + bx, 0.f);
            v0.y = fmaxf(acc[mt][nt][1] + by, 0.f);
            v1.x = fmaxf(acc[mt][nt][2] + bx, 0.f);
            v1.y = fmaxf(acc[mt][nt][3] + by, 0.f);
            *(float2*)(C + (size_t)rowa * HDIM + col) = v0;
            *(float2*)(C + (size_t)(rowa + 8) * HDIM + col) = v1;
        }
    }
}

// ---------------- GEMM2: logits = h @ W2 + b2 (one warp per token) ----------------
__global__ void gemm2_kernel(const float* __restrict__ h, const float* __restrict__ W2,
                             const float* __restrict__ b2, float* __restrict__ logits)
{
    int warp = (blockIdx.x * blockDim.x + threadIdx.x) >> 5;
    int lane = threadIdx.x & 31;
    if (warp >= NTOK) return;
    const float* hr = h + (size_t)warp * HDIM;

    float acc[NEXP];
    #pragma unroll
    for (int e = 0; e < NEXP; e++) acc[e] = 0.f;

    for (int k0 = lane * 4; k0 < HDIM; k0 += 128) {
        float4 hv = *(const float4*)(hr + k0);
        float hvv[4] = {hv.x, hv.y, hv.z, hv.w};
        #pragma unroll
        for (int j = 0; j < 4; j++) {
            const float* w = W2 + (size_t)(k0 + j) * NEXP;
            float4 w0 = *(const float4*)w;
            float4 w1 = *(const float4*)(w + 4);
            acc[0] += hvv[j] * w0.x; acc[1] += hvv[j] * w0.y;
            acc[2] += hvv[j] * w0.z; acc[3] += hvv[j] * w0.w;
            acc[4] += hvv[j] * w1.x; acc[5] += hvv[j] * w1.y;
            acc[6] += hvv[j] * w1.z; acc[7] += hvv[j] * w1.w;
        }
    }
    #pragma unroll
    for (int e = 0; e < NEXP; e++) {
        #pragma unroll
        for (int off = 16; off > 0; off >>= 1)
            acc[e] += __shfl_down_sync(0xffffffffu, acc[e], off);
    }
    if (lane == 0) {
        #pragma unroll
        for (int e = 0; e < NEXP; e++)
            logits[warp * NEXP + e] = acc[e] + b2[e];
    }
}

// ---------------- softmax + top-2 ----------------
__global__ void topk_kernel(const float* __restrict__ logits, float* __restrict__ probs_out)
{
    int t = blockIdx.x * blockDim.x + threadIdx.x;
    if (t >= NTOK) return;
    float l[NEXP];
    float m = -1e30f;
    #pragma unroll
    for (int e = 0; e < NEXP; e++) { l[e] = logits[t * NEXP + e]; m = fmaxf(m, l[e]); }
    float s = 0.f;
    #pragma unroll
    for (int e = 0; e < NEXP; e++) { l[e] = expf(l[e] - m); s += l[e]; }
    float inv = 1.f / s;
    float p[NEXP];
    #pragma unroll
    for (int e = 0; e < NEXP; e++) { p[e] = l[e] * inv; probs_out[t * NEXP + e] = p[e]; }

    int i1 = 0; float p1 = p[0];
    #pragma unroll
    for (int e = 1; e < NEXP; e++) if (p[e] > p1) { p1 = p[e]; i1 = e; }
    int i2 = -1; float p2 = -1.f;
    #pragma unroll
    for (int e = 0; e < NEXP; e++) if (e != i1 && p[e] > p2) { p2 = p[e]; i2 = e; }

    float norm = 1.f / (p1 + p2 + 1e-8f);
    g_flat_idx[2 * t + 0] = i1;
    g_flat_idx[2 * t + 1] = i2;
    g_flat_prob[2 * t + 0] = p1 * norm;
    g_flat_prob[2 * t + 1] = p2 * norm;
    atomicAdd(&g_counts[i1], 1);
    atomicAdd(&g_counts[i2], 1);
}

// ---------------- exclusive per-expert position scan ----------------
__device__ __forceinline__ uint4 add4(uint4 a, uint4 b) {
    return make_uint4(a.x + b.x, a.y + b.y, a.z + b.z, a.w + b.w);
}
__device__ __forceinline__ uint4 sub4(uint4 a, uint4 b) {
    return make_uint4(a.x - b.x, a.y - b.y, a.z - b.z, a.w - b.w);
}
__global__ __launch_bounds__(1024) void scan_kernel()
{
    const int tid = threadIdx.x;
    const int lane = tid & 31, wid = tid >> 5;

    int e[8];
    uint4 pre[8];
    uint4 run = make_uint4(0, 0, 0, 0);
    #pragma unroll
    for (int i = 0; i < 8; i++) {
        e[i] = g_flat_idx[tid * 8 + i];
        pre[i] = run;
        unsigned word = (unsigned)e[i] >> 1;
        unsigned add = 1u << ((e[i] & 1) * 16);
        if (word == 0) run.x += add;
        else if (word == 1) run.y += add;
        else if (word == 2) run.z += add;
        else run.w += add;
    }
    const uint4 own = run;

    uint4 incl = own;
    #pragma unroll
    for (int off = 1; off < 32; off <<= 1) {
        unsigned vx = __shfl_up_sync(0xffffffffu, incl.x, off);
        unsigned vy = __shfl_up_sync(0xffffffffu, incl.y, off);
        unsigned vz = __shfl_up_sync(0xffffffffu, incl.z, off);
        unsigned vw = __shfl_up_sync(0xffffffffu, incl.w, off);
        if (lane >= off) { incl.x += vx; incl.y += vy; incl.z += vz; incl.w += vw; }
    }

    __shared__ uint4 wtot[32];
    if (lane == 31) wtot[wid] = incl;
    __syncthreads();
    if (wid == 0) {
        uint4 v = wtot[lane];
        uint4 inc2 = v;
        #pragma unroll
        for (int off = 1; off < 32; off <<= 1) {
            unsigned vx = __shfl_up_sync(0xffffffffu, inc2.x, off);
            unsigned vy = __shfl_up_sync(0xffffffffu, inc2.y, off);
            unsigned vz = __shfl_up_sync(0xffffffffu, inc2.z, off);
            unsigned vw = __shfl_up_sync(0xffffffffu, inc2.w, off);
            if (lane >= off) { inc2.x += vx; inc2.y += vy; inc2.z += vz; inc2.w += vw; }
        }
        wtot[lane] = sub4(inc2, v);
    }
    __syncthreads();

    const uint4 base = add4(wtot[wid], sub4(incl, own));
    #pragma unroll
    for (int i = 0; i < 8; i++) {
        uint4 tot = add4(base, pre[i]);
        unsigned word = (unsigned)e[i] >> 1;
        unsigned w = (word == 0) ? tot.x : (word == 1) ? tot.y : (word == 2) ? tot.z : tot.w;
        g_pos[tid * 8 + i] = (int)((w >> ((e[i] & 1) * 16)) & 0xFFFFu);
    }
}

// ---------------- scatter ----------------
__global__ void scatter_kernel(float* __restrict__ dispatch, float* __restrict__ combine)
{
    int n = blockIdx.x * blockDim.x + threadIdx.x;
    if (n >= NSEL) return;
    int p = g_pos[n];
    if (p < CAP) {
        int tok = n >> 1;
        int e = g_flat_idx[n];
        size_t off = ((size_t)tok * NEXP + e) * CAP + p;
        dispatch[off] = 1.0f;
        combine[off] = g_flat_prob[n];
    }
}

// ---------------- aux loss ----------------
__global__ void aux_kernel(const float* __restrict__ probs, float* __restrict__ aux_out)
{
    __shared__ float sh[256];
    const int tid = threadIdx.x;
    float local[NEXP];
    #pragma unroll
    for (int e = 0; e < NEXP; e++) local[e] = 0.f;
    for (int t = tid; t < NTOK; t += 256) {
        #pragma unroll
        for (int e = 0; e < NEXP; e++) local[e] += probs[t * NEXP + e];
    }
    float aux = 0.f;
    for (int e = 0; e < NEXP; e++) {
        sh[tid] = local[e];
        __syncthreads();
        for (int s = 128; s > 0; s >>= 1) {
            if (tid < s) sh[tid] += sh[tid + s];
            __syncthreads();
        }
        if (tid == 0)
            aux += (sh[0] / (float)NTOK) * ((float)g_counts[e] / (float)NSEL) * (float)NEXP;
        __syncthreads();
    }
    if (tid == 0) *aux_out = aux;
}

// ---------------- launch ----------------
extern "C" void kernel_launch(void* const* d_in, const int* in_sizes, int n_in,
                              void* d_out, int out_size)
{
    const float* x  = (const float*)d_in[0];
    const float* W1 = (const float*)d_in[1];
    const float* b1 = (const float*)d_in[2];
    const float* W2 = (const float*)d_in[3];
    const float* b2 = (const float*)d_in[4];

    float* out      = (float*)d_out;
    float* dispatch = out;
    float* combine  = out + DISPATCH_ELEMS;
    float* probs    = out + PROBS_OFF;
    float* aux      = out + AUX_OFF;

    float* d_h;      cudaGetSymbolAddress((void**)&d_h, g_h);
    float* d_logits; cudaGetSymbolAddress((void**)&d_logits, g_logits);

    static bool attr_set = false;
    if (!attr_set) {
        cudaFuncSetAttribute(gemm1_tc, cudaFuncAttributeMaxDynamicSharedMemorySize, GSMEM);
        attr_set = true;
    }

    // 1) zero dispatch + combine (+ counters)
    zero_kernel<<<4096, 256>>>((float4*)out, (2LL * DISPATCH_ELEMS) / 4);

    // 2) GEMM1 on tensor cores (3xTF32 mma.sync): h = relu(x@W1 + b1)
    gemm1_tc<<<dim3(HDIM / BN, NTOK / BM), 256, GSMEM>>>(x, W1, b1, d_h);

    // 3) GEMM2
    gemm2_kernel<<<NTOK / 8, 256>>>(d_h, W2, b2, d_logits);

    // 4) softmax + top-2
    topk_kernel<<<NTOK / 256, 256>>>(d_logits, probs);

    // 5) capacity position scan
    scan_kernel<<<1, 1024>>>();

    // 6) scatter
    scatter_kernel<<<NSEL / 256, 256>>>(dispatch, combine);

    // 7) aux loss
    aux_kernel<<<1, 256>>>(probs, aux);
}